// round 2
// baseline (speedup 1.0000x reference)
#include <cuda_runtime.h>
#include <math.h>

// Problem constants
#define Bn    4
#define Nn    50000
#define CF    32
#define GRES  32
#define PRES  128
#define HID   256
#define CDIM  128
#define NBLK  5

#define TILE     64
#define THREADS  256
#define TOTALP   (Bn * Nn)          // 200000
#define NBLOCKS  (TOTALP / TILE)    // 3125 (exact)

// ---------- packed f32x2 helpers ----------
__device__ __forceinline__ unsigned long long pk2(float lo, float hi) {
    unsigned long long r;
    asm("mov.b64 %0, {%1, %2};" : "=l"(r)
        : "r"(__float_as_uint(lo)), "r"(__float_as_uint(hi)));
    return r;
}
__device__ __forceinline__ void fma2(unsigned long long& d,
                                     unsigned long long a,
                                     unsigned long long b) {
    asm("fma.rn.f32x2 %0, %1, %2, %0;" : "+l"(d) : "l"(a), "l"(b));
}
__device__ __forceinline__ void upk2(unsigned long long v, float& lo, float& hi) {
    unsigned int a, b;
    asm("mov.b64 {%0, %1}, %2;" : "=r"(a), "=r"(b) : "l"(v));
    lo = __uint_as_float(a);
    hi = __uint_as_float(b);
}

// ---------- shared-memory tile ----------
struct SM {
    float net[TILE * HID];     // 64 KB
    float hbuf[TILE * HID];    // 64 KB
    float cfeat[TILE * CDIM];  // 32 KB
    float px[TILE], py[TILE], pz[TILE];
    int   bq[TILE];
    int   gx0[TILE], gy0[TILE], gz0[TILE];
    float gwx[TILE], gwy[TILE], gwz[TILE];
    int   qx0[TILE], qy0[TILE], qz0[TILE];
    float qwx[TILE], qwy[TILE], qwz[TILE];
};

// ---------- register-tiled GEMM: 64xK (smem) @ KxHID (gmem) ----------
// thread (ty,tx): ty=warp 0..7 owns points ty*8..ty*8+7; tx=lane owns cols
// {2*tx + 64*jj, +1} for jj=0..3. acc[pp][jj] is a packed f32x2 pair.
template <int K, bool RELU_IN>
__device__ __forceinline__ void mm_tile(const float* __restrict__ A,
                                        const float* __restrict__ W,
                                        int ty, int tx,
                                        unsigned long long acc[8][4]) {
#pragma unroll
    for (int pp = 0; pp < 8; pp++)
#pragma unroll
        for (int jj = 0; jj < 4; jj++) acc[pp][jj] = 0ull;

    const unsigned long long* __restrict__ W2 =
        reinterpret_cast<const unsigned long long*>(W);

#pragma unroll 2
    for (int k = 0; k < K; k++) {
        unsigned long long av[8];
#pragma unroll
        for (int pp = 0; pp < 8; pp++) {
            float v = A[(ty * 8 + pp) * K + k];     // warp-broadcast LDS
            if (RELU_IN) v = fmaxf(v, 0.0f);
            av[pp] = pk2(v, v);
        }
        unsigned long long wv[4];
#pragma unroll
        for (int jj = 0; jj < 4; jj++)
            wv[jj] = __ldg(W2 + (size_t)k * (HID / 2) + tx + 32 * jj);
#pragma unroll
        for (int pp = 0; pp < 8; pp++)
#pragma unroll
            for (int jj = 0; jj < 4; jj++)
                fma2(acc[pp][jj], av[pp], wv[jj]);
    }
}

__device__ __forceinline__ float bilin(const float* __restrict__ base,
                                       int ix, int iy, float wu, float wv) {
    int o = (iy << 7) + ix;            // PRES = 128
    float a = base[o],       b = base[o + 1];
    float c = base[o + 128], d = base[o + 129];
    float t0 = a + (b - a) * wu;
    float t1 = c + (d - c) * wu;
    return t0 + (t1 - t0) * wv;
}

__global__ void __launch_bounds__(THREADS, 1)
decoder_kernel(const float* __restrict__ p,
               const float* __restrict__ c_grid,
               const float* __restrict__ c_xy,
               const float* __restrict__ c_yz,
               const float* __restrict__ c_xz,
               const float* __restrict__ Wp,  const float* __restrict__ bp,
               const float* __restrict__ Wc,  const float* __restrict__ bc,
               const float* __restrict__ W0,  const float* __restrict__ b0,
               const float* __restrict__ W1,  const float* __restrict__ b1,
               const float* __restrict__ Wout,const float* __restrict__ bout,
               float* __restrict__ out) {
    extern __shared__ char smem_raw[];
    SM& s = *reinterpret_cast<SM*>(smem_raw);

    const int tid = threadIdx.x;
    const int ty  = tid >> 5;
    const int tx  = tid & 31;
    const int q0  = blockIdx.x * TILE;

    // ---- per-point coordinate prep (64 threads) ----
    if (tid < TILE) {
        int q = q0 + tid;
        float x = p[q * 3 + 0], y = p[q * 3 + 1], z = p[q * 3 + 2];
        s.px[tid] = x; s.py[tid] = y; s.pz[tid] = z;
        s.bq[tid] = q / Nn;

        // normalize: xn = x/1.101 + 0.5, clip [0, 1-1e-5]
        float xn = fminf(fmaxf(x / 1.101f + 0.5f, 0.0f), 1.0f - 1e-5f);
        float yn = fminf(fmaxf(y / 1.101f + 0.5f, 0.0f), 1.0f - 1e-5f);
        float zn = fminf(fmaxf(z / 1.101f + 0.5f, 0.0f), 1.0f - 1e-5f);

        // grid (res 32): ix = xn*(GRES-1)
        float fgx = xn * (GRES - 1), fgy = yn * (GRES - 1), fgz = zn * (GRES - 1);
        int gx = (int)floorf(fgx), gy = (int)floorf(fgy), gz = (int)floorf(fgz);
        s.gx0[tid] = gx; s.gy0[tid] = gy; s.gz0[tid] = gz;
        s.gwx[tid] = fgx - gx; s.gwy[tid] = fgy - gy; s.gwz[tid] = fgz - gz;

        // planes (res 128)
        float fpx = xn * (PRES - 1), fpy = yn * (PRES - 1), fpz = zn * (PRES - 1);
        int px0 = (int)floorf(fpx), py0 = (int)floorf(fpy), pz0 = (int)floorf(fpz);
        s.qx0[tid] = px0; s.qy0[tid] = py0; s.qz0[tid] = pz0;
        s.qwx[tid] = fpx - px0; s.qwy[tid] = fpy - py0; s.qwz[tid] = fpz - pz0;
    }
    __syncthreads();

    // ---- feature interpolation: 64 pts x 32 ch, 8 tasks/thread ----
    for (int task = tid; task < TILE * CF; task += THREADS) {
        int pp = task >> 5;
        int ch = task & 31;
        int bq = s.bq[pp];
        int bc_ch = bq * CF + ch;

        // trilinear on grid
        {
            const float* g = c_grid + ((size_t)bc_ch << 15);  // 32^3
            int o = (s.gz0[pp] << 10) + (s.gy0[pp] << 5) + s.gx0[pp];
            float wx = s.gwx[pp], wy = s.gwy[pp], wz = s.gwz[pp];
            float v000 = g[o],        v001 = g[o + 1];
            float v010 = g[o + 32],   v011 = g[o + 33];
            float v100 = g[o + 1024], v101 = g[o + 1025];
            float v110 = g[o + 1056], v111 = g[o + 1057];
            float c00 = v000 + (v001 - v000) * wx;
            float c01 = v010 + (v011 - v010) * wx;
            float c10 = v100 + (v101 - v100) * wx;
            float c11 = v110 + (v111 - v110) * wx;
            float cz0 = c00 + (c01 - c00) * wy;
            float cz1 = c10 + (c11 - c10) * wy;
            s.cfeat[pp * CDIM + ch] = cz0 + (cz1 - cz0) * wz;
        }
        // planes
        {
            size_t poff = (size_t)bc_ch << 14;  // 128^2
            int x0 = s.qx0[pp], y0 = s.qy0[pp], z0 = s.qz0[pp];
            float wx = s.qwx[pp], wy = s.qwy[pp], wz = s.qwz[pp];
            s.cfeat[pp * CDIM + 32 + ch] = bilin(c_xy + poff, x0, y0, wx, wy);
            s.cfeat[pp * CDIM + 64 + ch] = bilin(c_yz + poff, y0, z0, wy, wz);
            s.cfeat[pp * CDIM + 96 + ch] = bilin(c_xz + poff, x0, z0, wx, wz);
        }
    }

    // ---- net init: net = p @ Wp + bp ----
    for (int idx = tid; idx < TILE * HID; idx += THREADS) {
        int pp = idx >> 8;
        int h  = idx & (HID - 1);
        float v = s.px[pp] * Wp[h] + s.py[pp] * Wp[HID + h]
                + s.pz[pp] * Wp[2 * HID + h] + bp[h];
        s.net[pp * HID + h] = v;
    }
    __syncthreads();

    unsigned long long acc[8][4];

    // ---- 5 residual blocks ----
    for (int blk = 0; blk < NBLK; blk++) {
        const float* WcL = Wc + (size_t)blk * CDIM * HID;
        const float* bcL = bc + blk * HID;
        const float* W0L = W0 + (size_t)blk * HID * HID;
        const float* b0L = b0 + blk * HID;
        const float* W1L = W1 + (size_t)blk * HID * HID;
        const float* b1L = b1 + blk * HID;

        // (a) net += c @ Wc + bc
        mm_tile<CDIM, false>(s.cfeat, WcL, ty, tx, acc);
#pragma unroll
        for (int pp = 0; pp < 8; pp++) {
            int row = (ty * 8 + pp) * HID;
#pragma unroll
            for (int jj = 0; jj < 4; jj++) {
                float lo, hi; upk2(acc[pp][jj], lo, hi);
                int j0 = 2 * tx + 64 * jj;
                s.net[row + j0]     += lo + bcL[j0];
                s.net[row + j0 + 1] += hi + bcL[j0 + 1];
            }
        }
        __syncthreads();

        // (b) h = relu( relu(net) @ W0 + b0 )   (store relu'd)
        mm_tile<HID, true>(s.net, W0L, ty, tx, acc);
#pragma unroll
        for (int pp = 0; pp < 8; pp++) {
            int row = (ty * 8 + pp) * HID;
#pragma unroll
            for (int jj = 0; jj < 4; jj++) {
                float lo, hi; upk2(acc[pp][jj], lo, hi);
                int j0 = 2 * tx + 64 * jj;
                s.hbuf[row + j0]     = fmaxf(lo + b0L[j0], 0.0f);
                s.hbuf[row + j0 + 1] = fmaxf(hi + b0L[j0 + 1], 0.0f);
            }
        }
        __syncthreads();

        // (c) net += h @ W1 + b1
        mm_tile<HID, false>(s.hbuf, W1L, ty, tx, acc);
#pragma unroll
        for (int pp = 0; pp < 8; pp++) {
            int row = (ty * 8 + pp) * HID;
#pragma unroll
            for (int jj = 0; jj < 4; jj++) {
                float lo, hi; upk2(acc[pp][jj], lo, hi);
                int j0 = 2 * tx + 64 * jj;
                s.net[row + j0]     += lo + b1L[j0];
                s.net[row + j0 + 1] += hi + b1L[j0 + 1];
            }
        }
        __syncthreads();
    }

    // ---- output: out = relu(net) @ Wout + bout (warp handles 8 points) ----
    float boutv = bout[0];
#pragma unroll
    for (int pp = 0; pp < 8; pp++) {
        int pt = ty * 8 + pp;
        float partial = 0.0f;
        const float* row = s.net + pt * HID;
#pragma unroll 4
        for (int k = tx; k < HID; k += 32)
            partial += fmaxf(row[k], 0.0f) * Wout[k];
#pragma unroll
        for (int off = 16; off > 0; off >>= 1)
            partial += __shfl_xor_sync(0xFFFFFFFFu, partial, off);
        if (tx == 0) out[q0 + pt] = partial + boutv;
    }
}

extern "C" void kernel_launch(void* const* d_in, const int* in_sizes, int n_in,
                              void* d_out, int out_size) {
    const float* p      = (const float*)d_in[0];
    const float* c_grid = (const float*)d_in[1];
    const float* c_xy   = (const float*)d_in[2];
    const float* c_yz   = (const float*)d_in[3];
    const float* c_xz   = (const float*)d_in[4];
    const float* Wp     = (const float*)d_in[5];
    const float* bp     = (const float*)d_in[6];
    const float* Wc     = (const float*)d_in[7];
    const float* bc     = (const float*)d_in[8];
    const float* W0     = (const float*)d_in[9];
    const float* b0     = (const float*)d_in[10];
    const float* W1     = (const float*)d_in[11];
    const float* b1     = (const float*)d_in[12];
    const float* Wout   = (const float*)d_in[13];
    const float* bout   = (const float*)d_in[14];
    float* out = (float*)d_out;

    int smem = (int)sizeof(SM);
    static bool attr_set = false;
    if (!attr_set) {
        cudaFuncSetAttribute(decoder_kernel,
                             cudaFuncAttributeMaxDynamicSharedMemorySize, smem);
        attr_set = true;
    }
    decoder_kernel<<<NBLOCKS, THREADS, smem>>>(
        p, c_grid, c_xy, c_yz, c_xz, Wp, bp, Wc, bc, W0, b0, W1, b1,
        Wout, bout, out);
}

// round 5
// speedup vs baseline: 1.5138x; 1.5138x over previous
#include <cuda_runtime.h>
#include <math.h>

// Problem constants
#define Bn    4
#define Nn    50000
#define CF    32
#define GRES  32
#define PRES  128
#define HID   256
#define CDIM  128
#define NBLK  5

#define TILE     32
#define PPW      4                  // points per warp (TILE / 8 warps)
#define THREADS  256
#define TOTALP   (Bn * Nn)          // 200000
#define NBLOCKS  (TOTALP / TILE)    // 6250 (exact)

// ---------- packed f32x2 helpers ----------
__device__ __forceinline__ unsigned long long pk2(float lo, float hi) {
    unsigned long long r;
    asm("mov.b64 %0, {%1, %2};" : "=l"(r)
        : "r"(__float_as_uint(lo)), "r"(__float_as_uint(hi)));
    return r;
}
__device__ __forceinline__ void fma2(unsigned long long& d,
                                     unsigned long long a,
                                     unsigned long long b) {
    asm("fma.rn.f32x2 %0, %1, %2, %0;" : "+l"(d) : "l"(a), "l"(b));
}
__device__ __forceinline__ void upk2(unsigned long long v, float& lo, float& hi) {
    unsigned int a, b;
    asm("mov.b64 {%0, %1}, %2;" : "=r"(a), "=r"(b) : "l"(v));
    lo = __uint_as_float(a);
    hi = __uint_as_float(b);
}

// ---------- shared-memory tile (~83.5 KB -> 2 CTAs/SM) ----------
struct SM {
    float net[TILE * HID];     // 32 KB
    float hbuf[TILE * HID];    // 32 KB
    float cfeat[TILE * CDIM];  // 16 KB
    float px[TILE], py[TILE], pz[TILE];
    int   bq[TILE];
    int   gx0[TILE], gy0[TILE], gz0[TILE];
    float gwx[TILE], gwy[TILE], gwz[TILE];
    int   qx0[TILE], qy0[TILE], qz0[TILE];
    float qwx[TILE], qwy[TILE], qwz[TILE];
};

// ---------- register-tiled GEMM: TILExK (smem) @ KxHID (gmem) ----------
// warp ty owns points ty*4..ty*4+3; lane tx owns cols {2*tx + 64*jj, +1}.
template <int K, bool RELU_IN>
__device__ __forceinline__ void mm_tile(const float* __restrict__ A,
                                        const float* __restrict__ W,
                                        int ty, int tx,
                                        unsigned long long acc[PPW][4]) {
#pragma unroll
    for (int pp = 0; pp < PPW; pp++)
#pragma unroll
        for (int jj = 0; jj < 4; jj++) acc[pp][jj] = 0ull;

    const unsigned long long* __restrict__ W2 =
        reinterpret_cast<const unsigned long long*>(W);

#pragma unroll 4
    for (int k = 0; k < K; k++) {
        unsigned long long av[PPW];
#pragma unroll
        for (int pp = 0; pp < PPW; pp++) {
            float v = A[(ty * PPW + pp) * K + k];   // warp-broadcast LDS
            if (RELU_IN) v = fmaxf(v, 0.0f);
            av[pp] = pk2(v, v);
        }
        unsigned long long wv[4];
#pragma unroll
        for (int jj = 0; jj < 4; jj++)
            wv[jj] = __ldg(W2 + (size_t)k * (HID / 2) + tx + 32 * jj);
#pragma unroll
        for (int pp = 0; pp < PPW; pp++)
#pragma unroll
            for (int jj = 0; jj < 4; jj++)
                fma2(acc[pp][jj], av[pp], wv[jj]);
    }
}

__device__ __forceinline__ float bilin(const float* __restrict__ base,
                                       int ix, int iy, float wu, float wv) {
    int o = (iy << 7) + ix;            // PRES = 128
    float a = base[o],       b = base[o + 1];
    float c = base[o + 128], d = base[o + 129];
    float t0 = a + (b - a) * wu;
    float t1 = c + (d - c) * wu;
    return t0 + (t1 - t0) * wv;
}

__global__ void __launch_bounds__(THREADS, 2)
decoder_kernel(const float* __restrict__ p,
               const float* __restrict__ c_grid,
               const float* __restrict__ c_xy,
               const float* __restrict__ c_yz,
               const float* __restrict__ c_xz,
               const float* __restrict__ Wp,  const float* __restrict__ bp,
               const float* __restrict__ Wc,  const float* __restrict__ bc,
               const float* __restrict__ W0,  const float* __restrict__ b0,
               const float* __restrict__ W1,  const float* __restrict__ b1,
               const float* __restrict__ Wout,const float* __restrict__ bout,
               float* __restrict__ out) {
    extern __shared__ char smem_raw[];
    SM& s = *reinterpret_cast<SM*>(smem_raw);

    const int tid = threadIdx.x;
    const int ty  = tid >> 5;
    const int tx  = tid & 31;
    const int q0  = blockIdx.x * TILE;

    // ---- per-point coordinate prep (32 threads) ----
    if (tid < TILE) {
        int q = q0 + tid;
        float x = p[q * 3 + 0], y = p[q * 3 + 1], z = p[q * 3 + 2];
        s.px[tid] = x; s.py[tid] = y; s.pz[tid] = z;
        s.bq[tid] = q / Nn;

        float xn = fminf(fmaxf(x / 1.101f + 0.5f, 0.0f), 1.0f - 1e-5f);
        float yn = fminf(fmaxf(y / 1.101f + 0.5f, 0.0f), 1.0f - 1e-5f);
        float zn = fminf(fmaxf(z / 1.101f + 0.5f, 0.0f), 1.0f - 1e-5f);

        float fgx = xn * (GRES - 1), fgy = yn * (GRES - 1), fgz = zn * (GRES - 1);
        int gx = (int)floorf(fgx), gy = (int)floorf(fgy), gz = (int)floorf(fgz);
        s.gx0[tid] = gx; s.gy0[tid] = gy; s.gz0[tid] = gz;
        s.gwx[tid] = fgx - gx; s.gwy[tid] = fgy - gy; s.gwz[tid] = fgz - gz;

        float fpx = xn * (PRES - 1), fpy = yn * (PRES - 1), fpz = zn * (PRES - 1);
        int px0 = (int)floorf(fpx), py0 = (int)floorf(fpy), pz0 = (int)floorf(fpz);
        s.qx0[tid] = px0; s.qy0[tid] = py0; s.qz0[tid] = pz0;
        s.qwx[tid] = fpx - px0; s.qwy[tid] = fpy - py0; s.qwz[tid] = fpz - pz0;
    }
    __syncthreads();

    // ---- feature interpolation: 32 pts x 32 ch, 4 tasks/thread ----
    for (int task = tid; task < TILE * CF; task += THREADS) {
        int pp = task >> 5;
        int ch = task & 31;
        int bq = s.bq[pp];
        int bc_ch = bq * CF + ch;

        // trilinear on grid
        {
            const float* g = c_grid + ((size_t)bc_ch << 15);  // 32^3
            int o = (s.gz0[pp] << 10) + (s.gy0[pp] << 5) + s.gx0[pp];
            float wx = s.gwx[pp], wy = s.gwy[pp], wz = s.gwz[pp];
            float v000 = g[o],        v001 = g[o + 1];
            float v010 = g[o + 32],   v011 = g[o + 33];
            float v100 = g[o + 1024], v101 = g[o + 1025];
            float v110 = g[o + 1056], v111 = g[o + 1057];
            float c00 = v000 + (v001 - v000) * wx;
            float c01 = v010 + (v011 - v010) * wx;
            float c10 = v100 + (v101 - v100) * wx;
            float c11 = v110 + (v111 - v110) * wx;
            float cz0 = c00 + (c01 - c00) * wy;
            float cz1 = c10 + (c11 - c10) * wy;
            s.cfeat[pp * CDIM + ch] = cz0 + (cz1 - cz0) * wz;
        }
        // planes
        {
            size_t poff = (size_t)bc_ch << 14;  // 128^2
            int x0 = s.qx0[pp], y0 = s.qy0[pp], z0 = s.qz0[pp];
            float wx = s.qwx[pp], wy = s.qwy[pp], wz = s.qwz[pp];
            s.cfeat[pp * CDIM + 32 + ch] = bilin(c_xy + poff, x0, y0, wx, wy);
            s.cfeat[pp * CDIM + 64 + ch] = bilin(c_yz + poff, y0, z0, wy, wz);
            s.cfeat[pp * CDIM + 96 + ch] = bilin(c_xz + poff, x0, z0, wx, wz);
        }
    }

    // ---- net init: net = p @ Wp + bp ----
    for (int idx = tid; idx < TILE * HID; idx += THREADS) {
        int pp = idx >> 8;
        int h  = idx & (HID - 1);
        float v = s.px[pp] * Wp[h] + s.py[pp] * Wp[HID + h]
                + s.pz[pp] * Wp[2 * HID + h] + bp[h];
        s.net[pp * HID + h] = v;
    }
    __syncthreads();

    unsigned long long acc[PPW][4];

    // ---- 5 residual blocks ----
    for (int blk = 0; blk < NBLK; blk++) {
        const float* WcL = Wc + (size_t)blk * CDIM * HID;
        const float* bcL = bc + blk * HID;
        const float* W0L = W0 + (size_t)blk * HID * HID;
        const float* b0L = b0 + blk * HID;
        const float* W1L = W1 + (size_t)blk * HID * HID;
        const float* b1L = b1 + blk * HID;

        // (a) net += c @ Wc + bc
        mm_tile<CDIM, false>(s.cfeat, WcL, ty, tx, acc);
#pragma unroll
        for (int pp = 0; pp < PPW; pp++) {
            int row = (ty * PPW + pp) * HID;
#pragma unroll
            for (int jj = 0; jj < 4; jj++) {
                float lo, hi; upk2(acc[pp][jj], lo, hi);
                int j0 = 2 * tx + 64 * jj;
                s.net[row + j0]     += lo + bcL[j0];
                s.net[row + j0 + 1] += hi + bcL[j0 + 1];
            }
        }
        __syncthreads();

        // (b) h = relu( relu(net) @ W0 + b0 )   (store relu'd)
        mm_tile<HID, true>(s.net, W0L, ty, tx, acc);
#pragma unroll
        for (int pp = 0; pp < PPW; pp++) {
            int row = (ty * PPW + pp) * HID;
#pragma unroll
            for (int jj = 0; jj < 4; jj++) {
                float lo, hi; upk2(acc[pp][jj], lo, hi);
                int j0 = 2 * tx + 64 * jj;
                s.hbuf[row + j0]     = fmaxf(lo + b0L[j0], 0.0f);
                s.hbuf[row + j0 + 1] = fmaxf(hi + b0L[j0 + 1], 0.0f);
            }
        }
        __syncthreads();

        // (c) net += h @ W1 + b1
        mm_tile<HID, false>(s.hbuf, W1L, ty, tx, acc);
#pragma unroll
        for (int pp = 0; pp < PPW; pp++) {
            int row = (ty * PPW + pp) * HID;
#pragma unroll
            for (int jj = 0; jj < 4; jj++) {
                float lo, hi; upk2(acc[pp][jj], lo, hi);
                int j0 = 2 * tx + 64 * jj;
                s.net[row + j0]     += lo + b1L[j0];
                s.net[row + j0 + 1] += hi + b1L[j0 + 1];
            }
        }
        __syncthreads();
    }

    // ---- output: out = relu(net) @ Wout + bout (warp handles 4 points) ----
    float boutv = bout[0];
#pragma unroll
    for (int pp = 0; pp < PPW; pp++) {
        int pt = ty * PPW + pp;
        float partial = 0.0f;
        const float* row = s.net + pt * HID;
#pragma unroll 4
        for (int k = tx; k < HID; k += 32)
            partial += fmaxf(row[k], 0.0f) * Wout[k];
#pragma unroll
        for (int off = 16; off > 0; off >>= 1)
            partial += __shfl_xor_sync(0xFFFFFFFFu, partial, off);
        if (tx == 0) out[q0 + pt] = partial + boutv;
    }
}

extern "C" void kernel_launch(void* const* d_in, const int* in_sizes, int n_in,
                              void* d_out, int out_size) {
    const float* p      = (const float*)d_in[0];
    const float* c_grid = (const float*)d_in[1];
    const float* c_xy   = (const float*)d_in[2];
    const float* c_yz   = (const float*)d_in[3];
    const float* c_xz   = (const float*)d_in[4];
    const float* Wp     = (const float*)d_in[5];
    const float* bp     = (const float*)d_in[6];
    const float* Wc     = (const float*)d_in[7];
    const float* bc     = (const float*)d_in[8];
    const float* W0     = (const float*)d_in[9];
    const float* b0     = (const float*)d_in[10];
    const float* W1     = (const float*)d_in[11];
    const float* b1     = (const float*)d_in[12];
    const float* Wout   = (const float*)d_in[13];
    const float* bout   = (const float*)d_in[14];
    float* out = (float*)d_out;

    int smem = (int)sizeof(SM);
    static bool attr_set = false;
    if (!attr_set) {
        cudaFuncSetAttribute(decoder_kernel,
                             cudaFuncAttributeMaxDynamicSharedMemorySize, smem);
        attr_set = true;
    }
    decoder_kernel<<<NBLOCKS, THREADS, smem>>>(
        p, c_grid, c_xy, c_yz, c_xz, Wp, bp, Wc, bc, W0, b0, W1, b1,
        Wout, bout, out);
}

// round 9
// speedup vs baseline: 4.1732x; 2.7567x over previous
#include <cuda_runtime.h>
#include <cuda_bf16.h>
#include <stdint.h>
#include <math.h>

#define TOTALP  200000
#define Nn      50000
#define CF      32
#define GRES    32
#define PRES    128
#define HID     256
#define NBLK    5

#define MT      64                   // points per CTA
#define THREADS 256                  // 8 warps: 2 warpM x 4 warpN
#define NBLOCKS (TOTALP / MT)        // 3125 exact

#define SF      136                  // feature smem row stride (bf16 elems, K=128 + pad 8)
#define SN      264                  // net smem row stride (bf16 elems, K=256 + pad 8)

// weight blob per-block layout (bytes): fragment-packed bf16 splits
#define L0S0 0                       // Wc hi   (K=128: 8 ktiles * 32 ntiles * 256B)
#define L0S1 65536                   // Wc lo
#define L1S0 131072                  // W0 hi   (K=256)
#define L1S1 262144                  // W0 lo
#define L2S0 393216                  // W1 hi
#define L2S1 524288                  // W1 lo
#define BLK_STRIDE 655360

__device__ __align__(16) unsigned char g_wblob[(size_t)NBLK * BLK_STRIDE];
__device__ float g_cum[(NBLK + 1) * HID];

// ---------------- low-level helpers ----------------
__device__ __forceinline__ uint32_t s2u(const void* p) {
    uint32_t a;
    asm("{ .reg .u64 t; cvta.to.shared.u64 t, %1; cvt.u32.u64 %0, t; }" : "=r"(a) : "l"(p));
    return a;
}
__device__ __forceinline__ uint32_t lds32(uint32_t a) {
    uint32_t v;
    asm volatile("ld.shared.b32 %0, [%1];" : "=r"(v) : "r"(a));
    return v;
}
__device__ __forceinline__ void sts32(uint32_t a, uint32_t v) {
    asm volatile("st.shared.b32 [%0], %1;" :: "r"(a), "r"(v) : "memory");
}
__device__ __forceinline__ void sts16(uint32_t a, unsigned short v) {
    asm volatile("st.shared.u16 [%0], %1;" :: "r"(a), "h"(v) : "memory");
}
// m16n8k16 bf16 mma, acc fp32
__device__ __forceinline__ void mma16816(float* d, const uint32_t* a, const uint32_t* b) {
    asm volatile(
        "mma.sync.aligned.m16n8k16.row.col.f32.bf16.bf16.f32 "
        "{%0,%1,%2,%3}, {%4,%5,%6,%7}, {%8,%9}, {%0,%1,%2,%3};"
        : "+f"(d[0]), "+f"(d[1]), "+f"(d[2]), "+f"(d[3])
        : "r"(a[0]), "r"(a[1]), "r"(a[2]), "r"(a[3]), "r"(b[0]), "r"(b[1]));
}
__device__ __forceinline__ uint32_t pack_bf16(float v0, float v1) {
    __nv_bfloat16 h0 = __float2bfloat16(v0), h1 = __float2bfloat16(v1);
    return (uint32_t)__bfloat16_as_ushort(h0) | ((uint32_t)__bfloat16_as_ushort(h1) << 16);
}
__device__ __forceinline__ uint32_t pack_bf16_lo(float v0, float v1) {
    __nv_bfloat16 h0 = __float2bfloat16(v0), h1 = __float2bfloat16(v1);
    __nv_bfloat16 l0 = __float2bfloat16(v0 - __bfloat162float(h0));
    __nv_bfloat16 l1 = __float2bfloat16(v1 - __bfloat162float(h1));
    return (uint32_t)__bfloat16_as_ushort(l0) | ((uint32_t)__bfloat16_as_ushort(l1) << 16);
}

// ---------------- prep kernel: pack weights into fragment-native split blob ----------------
// Consumer: lane l of (ktile t, ntile j) loads 8B at ((t*32+j)*32+l)*8:
//   b0 = {W[k0][n], W[k0+1][n]}, b1 = {W[k0+8][n], W[k0+9][n]},
//   k0 = t*16 + (l&3)*2, n = j*8 + (l>>2)
__global__ void prep_kernel(const float* __restrict__ Wc, const float* __restrict__ W0,
                            const float* __restrict__ W1, const float* __restrict__ bp,
                            const float* __restrict__ bc, const float* __restrict__ b1) {
    const int total = NBLK * 640 * 256;
    for (int i = blockIdx.x * blockDim.x + threadIdx.x; i < total; i += gridDim.x * blockDim.x) {
        int blk = i / (640 * 256);
        int r   = i % (640 * 256);
        int k   = r / 256;
        int n   = r % 256;
        float w; size_t base; size_t lsz; int kl;
        if (k < 128)      { kl = k;       w = Wc[((size_t)blk * 128 + kl) * 256 + n]; base = (size_t)blk * BLK_STRIDE + L0S0; lsz = 65536; }
        else if (k < 384) { kl = k - 128; w = W0[((size_t)blk * 256 + kl) * 256 + n]; base = (size_t)blk * BLK_STRIDE + L1S0; lsz = 131072; }
        else              { kl = k - 384; w = W1[((size_t)blk * 256 + kl) * 256 + n]; base = (size_t)blk * BLK_STRIDE + L2S0; lsz = 131072; }
        __nv_bfloat16 h = __float2bfloat16(w);
        __nv_bfloat16 l = __float2bfloat16(w - __bfloat162float(h));
        int t = kl >> 4, kr = kl & 15;
        int j = n >> 3;
        int lane = ((n & 7) << 2) | ((kr & 7) >> 1);
        int reg = kr >> 3;
        size_t off = (size_t)((t * 32 + j) * 32 + lane) * 8 + reg * 4 + (kr & 1) * 2;
        *(unsigned short*)(g_wblob + base + off)       = __bfloat16_as_ushort(h);
        *(unsigned short*)(g_wblob + base + lsz + off) = __bfloat16_as_ushort(l);
    }
    if (blockIdx.x == 0 && threadIdx.x < 256) {
        int c = threadIdx.x;
        float pre = bp[c];
        for (int i = 0; i < NBLK; i++) {
            g_cum[i * 256 + c] = pre + bc[i * 256 + c];
            pre += bc[i * 256 + c] + b1[i * 256 + c];
        }
        g_cum[NBLK * 256 + c] = pre;
    }
}

// ---------------- shared memory ----------------
struct SMX {
    unsigned char feat0[MT * SF * 2];   // 17408: features hi (K=128, padded)
    unsigned char feat1[MT * SF * 2];   // features lo
    unsigned char na0[MT * SN * 2];     // 33792: activation hi (K=256, padded)
    unsigned char na1[MT * SN * 2];     // activation lo
    float px[MT], py[MT], pz[MT];
    int   bq[MT];
    int   gx0[MT], gy0[MT], gz0[MT];
    float gwx[MT], gwy[MT], gwz[MT];
    int   qx0[MT], qy0[MT], qz0[MT];
    float qwx[MT], qwy[MT], qwz[MT];
    float outp[MT][4];
};

__device__ __forceinline__ float bilin(const float* __restrict__ base,
                                       int ix, int iy, float wu, float wv) {
    int o = (iy << 7) + ix;
    float a = base[o], b = base[o + 1];
    float c = base[o + 128], d = base[o + 129];
    float t0 = a + (b - a) * wu;
    float t1 = c + (d - c) * wu;
    return t0 + (t1 - t0) * wv;
}

// 3-pass split GEMM: acc += A @ W  (A = A0+A1 in smem, W = W0+W1 fragment blob)
template <int KT>
__device__ __forceinline__ void gemm3(float acc[2][8][4],
                                      uint32_t aS0, uint32_t aS1, int strideE,
                                      const unsigned char* __restrict__ g0,
                                      const unsigned char* __restrict__ g1,
                                      int wM, int wN, int lane) {
    const int rowB = strideE * 2;
#pragma unroll 2
    for (int t = 0; t < KT; t++) {
        uint2 b0[8], b1[8];
        const uint2* p0 = reinterpret_cast<const uint2*>(g0) + ((t * 32 + wN * 8) * 32 + lane);
        const uint2* p1 = reinterpret_cast<const uint2*>(g1) + ((t * 32 + wN * 8) * 32 + lane);
#pragma unroll
        for (int nt = 0; nt < 8; nt++) { b0[nt] = __ldg(p0 + nt * 32); b1[nt] = __ldg(p1 + nt * 32); }
        uint32_t a0[2][4], a1[2][4];
#pragma unroll
        for (int mt = 0; mt < 2; mt++) {
            int R = wM * 32 + mt * 16 + (lane >> 2);
            int k = t * 16 + (lane & 3) * 2;
            uint32_t o0 = aS0 + (uint32_t)(R * rowB + k * 2);
            uint32_t o1 = aS1 + (uint32_t)(R * rowB + k * 2);
            a0[mt][0] = lds32(o0);
            a0[mt][1] = lds32(o0 + 8 * rowB);
            a0[mt][2] = lds32(o0 + 16);
            a0[mt][3] = lds32(o0 + 8 * rowB + 16);
            a1[mt][0] = lds32(o1);
            a1[mt][1] = lds32(o1 + 8 * rowB);
            a1[mt][2] = lds32(o1 + 16);
            a1[mt][3] = lds32(o1 + 8 * rowB + 16);
        }
#pragma unroll
        for (int mt = 0; mt < 2; mt++)
#pragma unroll
            for (int nt = 0; nt < 8; nt++) {
                mma16816(acc[mt][nt], a0[mt], (const uint32_t*)&b0[nt]);
                mma16816(acc[mt][nt], a1[mt], (const uint32_t*)&b0[nt]);
                mma16816(acc[mt][nt], a0[mt], (const uint32_t*)&b1[nt]);
            }
    }
}

// epilogue: write relu(acc + bias) as split bf16 into padded smem (A-layout)
__device__ __forceinline__ void epi_write(const float acc[2][8][4],
                                          const float* __restrict__ bias,
                                          uint32_t dst0, uint32_t dst1,
                                          int wM, int wN, int lane) {
    const int rowB = SN * 2;
#pragma unroll
    for (int mt = 0; mt < 2; mt++) {
        int Rb = wM * 32 + mt * 16 + (lane >> 2);
#pragma unroll
        for (int nt = 0; nt < 8; nt++) {
            int C = wN * 64 + nt * 8 + (lane & 3) * 2;
            float bb0 = __ldg(bias + C), bb1 = __ldg(bias + C + 1);
#pragma unroll
            for (int rh = 0; rh < 2; rh++) {
                float v0 = fmaxf(acc[mt][nt][rh * 2 + 0] + bb0, 0.0f);
                float v1 = fmaxf(acc[mt][nt][rh * 2 + 1] + bb1, 0.0f);
                uint32_t off = (uint32_t)((Rb + rh * 8) * rowB + C * 2);
                sts32(dst0 + off, pack_bf16(v0, v1));
                sts32(dst1 + off, pack_bf16_lo(v0, v1));
            }
        }
    }
}

__global__ void __launch_bounds__(THREADS, 1)
decoder_kernel(const float* __restrict__ p,
               const float* __restrict__ c_grid,
               const float* __restrict__ c_xy,
               const float* __restrict__ c_yz,
               const float* __restrict__ c_xz,
               const float* __restrict__ Wp,
               const float* __restrict__ b0g,
               const float* __restrict__ Wout,
               const float* __restrict__ bout,
               float* __restrict__ out) {
    extern __shared__ char smem_raw[];
    SMX& s = *reinterpret_cast<SMX*>(smem_raw);

    const int tid  = threadIdx.x;
    const int wid  = tid >> 5;
    const int lane = tid & 31;
    const int wM   = wid >> 2;      // 0..1
    const int wN   = wid & 3;       // 0..3
    const int q0   = blockIdx.x * MT;

    const uint32_t f0a = s2u(s.feat0), f1a = s2u(s.feat1);
    const uint32_t n0a = s2u(s.na0),   n1a = s2u(s.na1);

    // ---- coordinate prep ----
    if (tid < MT) {
        int q = q0 + tid;
        float x = p[q * 3 + 0], y = p[q * 3 + 1], z = p[q * 3 + 2];
        s.px[tid] = x; s.py[tid] = y; s.pz[tid] = z;
        s.bq[tid] = q / Nn;
        float xn = fminf(fmaxf(x / 1.101f + 0.5f, 0.0f), 1.0f - 1e-5f);
        float yn = fminf(fmaxf(y / 1.101f + 0.5f, 0.0f), 1.0f - 1e-5f);
        float zn = fminf(fmaxf(z / 1.101f + 0.5f, 0.0f), 1.0f - 1e-5f);
        float fgx = xn * (GRES - 1), fgy = yn * (GRES - 1), fgz = zn * (GRES - 1);
        int gx = (int)floorf(fgx), gy = (int)floorf(fgy), gz = (int)floorf(fgz);
        s.gx0[tid] = gx; s.gy0[tid] = gy; s.gz0[tid] = gz;
        s.gwx[tid] = fgx - gx; s.gwy[tid] = fgy - gy; s.gwz[tid] = fgz - gz;
        float fpx = xn * (PRES - 1), fpy = yn * (PRES - 1), fpz = zn * (PRES - 1);
        int px0 = (int)floorf(fpx), py0 = (int)floorf(fpy), pz0 = (int)floorf(fpz);
        s.qx0[tid] = px0; s.qy0[tid] = py0; s.qz0[tid] = pz0;
        s.qwx[tid] = fpx - px0; s.qwy[tid] = fpy - py0; s.qwz[tid] = fpz - pz0;
    }
    __syncthreads();

    // ---- features -> split bf16 feat buffers (padded row-major) ----
    for (int task = tid; task < MT * CF; task += THREADS) {
        int pp = task >> 5, ch = task & 31;
        int bc_ch = s.bq[pp] * CF + ch;
        float fv[4];
        {
            const float* g = c_grid + ((size_t)bc_ch << 15);
            int o = (s.gz0[pp] << 10) + (s.gy0[pp] << 5) + s.gx0[pp];
            float wx = s.gwx[pp], wy = s.gwy[pp], wz = s.gwz[pp];
            float v000 = g[o],        v001 = g[o + 1];
            float v010 = g[o + 32],   v011 = g[o + 33];
            float v100 = g[o + 1024], v101 = g[o + 1025];
            float v110 = g[o + 1056], v111 = g[o + 1057];
            float c00 = v000 + (v001 - v000) * wx;
            float c01 = v010 + (v011 - v010) * wx;
            float c10 = v100 + (v101 - v100) * wx;
            float c11 = v110 + (v111 - v110) * wx;
            float cz0 = c00 + (c01 - c00) * wy;
            float cz1 = c10 + (c11 - c10) * wy;
            fv[0] = cz0 + (cz1 - cz0) * wz;
        }
        {
            size_t poff = (size_t)bc_ch << 14;
            int x0 = s.qx0[pp], y0 = s.qy0[pp], z0 = s.qz0[pp];
            float wx = s.qwx[pp], wy = s.qwy[pp], wz = s.qwz[pp];
            fv[1] = bilin(c_xy + poff, x0, y0, wx, wy);
            fv[2] = bilin(c_yz + poff, y0, z0, wy, wz);
            fv[3] = bilin(c_xz + poff, x0, z0, wx, wz);
        }
#pragma unroll
        for (int fk = 0; fk < 4; fk++) {
            int k = fk * 32 + ch;
            __nv_bfloat16 h = __float2bfloat16(fv[fk]);
            __nv_bfloat16 l = __float2bfloat16(fv[fk] - __bfloat162float(h));
            uint32_t off = (uint32_t)((pp * SF + k) * 2);
            sts16(f0a + off, __bfloat16_as_ushort(h));
            sts16(f1a + off, __bfloat16_as_ushort(l));
        }
    }

    // ---- net acc init: netA = p @ Wp (biases folded into g_cum) ----
    float accN[2][8][4];
#pragma unroll
    for (int mt = 0; mt < 2; mt++) {
        int Rb = wM * 32 + mt * 16 + (lane >> 2);
#pragma unroll
        for (int nt = 0; nt < 8; nt++) {
            int C = wN * 64 + nt * 8 + (lane & 3) * 2;
            float w00 = __ldg(Wp + C),       w01 = __ldg(Wp + C + 1);
            float w10 = __ldg(Wp + 256 + C), w11 = __ldg(Wp + 256 + C + 1);
            float w20 = __ldg(Wp + 512 + C), w21 = __ldg(Wp + 512 + C + 1);
#pragma unroll
            for (int rh = 0; rh < 2; rh++) {
                int R = Rb + rh * 8;
                float x = s.px[R], y = s.py[R], z = s.pz[R];
                accN[mt][nt][rh * 2 + 0] = x * w00 + y * w10 + z * w20;
                accN[mt][nt][rh * 2 + 1] = x * w01 + y * w11 + z * w21;
            }
        }
    }
    __syncthreads();

    // ---- 5 residual blocks ----
    for (int blk = 0; blk < NBLK; blk++) {
        const unsigned char* bb = g_wblob + (size_t)blk * BLK_STRIDE;
        const float* cum = g_cum + blk * 256;
        const float* b0L = b0g + blk * 256;

        // (a) netA += c @ Wc
        gemm3<8>(accN, f0a, f1a, SF, bb + L0S0, bb + L0S1, wM, wN, lane);

        // (b) tmp = relu(netA + cum) @ W0
        __syncthreads();                       // prior readers of na done
        epi_write(accN, cum, n0a, n1a, wM, wN, lane);
        __syncthreads();
        float accT[2][8][4];
#pragma unroll
        for (int mt = 0; mt < 2; mt++)
#pragma unroll
            for (int nt = 0; nt < 8; nt++)
#pragma unroll
                for (int r4 = 0; r4 < 4; r4++) accT[mt][nt][r4] = 0.0f;
        gemm3<16>(accT, n0a, n1a, SN, bb + L1S0, bb + L1S1, wM, wN, lane);

        // (c) netA += relu(tmp + b0) @ W1
        __syncthreads();
        epi_write(accT, b0L, n0a, n1a, wM, wN, lane);
        __syncthreads();
        gemm3<16>(accN, n0a, n1a, SN, bb + L2S0, bb + L2S1, wM, wN, lane);
    }

    // ---- output: out = relu(netA + cumF) @ Wout + bout ----
    {
        const float* cumF = g_cum + NBLK * 256;
        float part[2][2] = {{0.f, 0.f}, {0.f, 0.f}};
#pragma unroll
        for (int mt = 0; mt < 2; mt++)
#pragma unroll
            for (int nt = 0; nt < 8; nt++) {
                int C = wN * 64 + nt * 8 + (lane & 3) * 2;
                float c0 = __ldg(cumF + C),   c1 = __ldg(cumF + C + 1);
                float w0 = __ldg(Wout + C),   w1 = __ldg(Wout + C + 1);
#pragma unroll
                for (int rh = 0; rh < 2; rh++) {
                    part[mt][rh] += fmaxf(accN[mt][nt][rh * 2 + 0] + c0, 0.0f) * w0
                                  + fmaxf(accN[mt][nt][rh * 2 + 1] + c1, 0.0f) * w1;
                }
            }
#pragma unroll
        for (int mt = 0; mt < 2; mt++)
#pragma unroll
            for (int rh = 0; rh < 2; rh++) {
                float v = part[mt][rh];
                v += __shfl_xor_sync(0xFFFFFFFFu, v, 1);
                v += __shfl_xor_sync(0xFFFFFFFFu, v, 2);
                if ((lane & 3) == 0) {
                    int R = wM * 32 + mt * 16 + (lane >> 2) + rh * 8;
                    s.outp[R][wN] = v;
                }
            }
        __syncthreads();
        if (tid < MT) {
            float v = s.outp[tid][0] + s.outp[tid][1] + s.outp[tid][2] + s.outp[tid][3]
                    + __ldg(bout);
            out[q0 + tid] = v;
        }
    }
}

extern "C" void kernel_launch(void* const* d_in, const int* in_sizes, int n_in,
                              void* d_out, int out_size) {
    const float* p      = (const float*)d_in[0];
    const float* c_grid = (const float*)d_in[1];
    const float* c_xy   = (const float*)d_in[2];
    const float* c_yz   = (const float*)d_in[3];
    const float* c_xz   = (const float*)d_in[4];
    const float* Wp     = (const float*)d_in[5];
    const float* bp     = (const float*)d_in[6];
    const float* Wc     = (const float*)d_in[7];
    const float* bc     = (const float*)d_in[8];
    const float* W0     = (const float*)d_in[9];
    const float* b0     = (const float*)d_in[10];
    const float* W1     = (const float*)d_in[11];
    const float* b1     = (const float*)d_in[12];
    const float* Wout   = (const float*)d_in[13];
    const float* bout   = (const float*)d_in[14];
    float* out = (float*)d_out;

    int smem = (int)sizeof(SMX);
    cudaFuncSetAttribute(decoder_kernel,
                         cudaFuncAttributeMaxDynamicSharedMemorySize, smem);

    prep_kernel<<<256, 256>>>(Wc, W0, W1, bp, bc, b1);
    decoder_kernel<<<NBLOCKS, THREADS, smem>>>(
        p, c_grid, c_xy, c_yz, c_xz, Wp, b0, Wout, bout, out);
}